// round 3
// baseline (speedup 1.0000x reference)
#include <cuda_runtime.h>
#include <math.h>

#define SQ 2048
#define DQ 512
#define NBATCH 8
#define MROWS (NBATCH * SQ)   // 16384

// ---- scratch (device globals: allocation-free) ----
__device__ float g_q[(size_t)MROWS * DQ];
__device__ float g_k[(size_t)MROWS * DQ];
__device__ float g_v[(size_t)MROWS * DQ];
__device__ float g_tmax[MROWS * 16];
__device__ float g_tsum[MROWS * 16];

// ============================================================================
// Generic NN GEMM: C[M,N] = A[M,K] * B[K,N], all row-major, optional batch (z).
// 128x128 CTA tile, BK=16, 256 threads, 8x8 per thread, reg-prefetch pipeline.
// Requires M%128==0, N%128==0, K%16==0 (true for all uses here).
// ============================================================================
__global__ __launch_bounds__(256, 2)
void gemm_nn_kernel(const float* __restrict__ A, const float* __restrict__ B,
                    float* __restrict__ C, int M, int N, int K,
                    long long sA, long long sB, long long sC)
{
    A += (long long)blockIdx.z * sA;
    B += (long long)blockIdx.z * sB;
    C += (long long)blockIdx.z * sC;
    const int bm = blockIdx.y << 7;
    const int bn = blockIdx.x << 7;

    __shared__ float As[16][132];   // transposed A tile [k][m], padded
    __shared__ float Bs[16][128];   // B tile [k][n]

    const int tid = threadIdx.x;
    const int tx = tid & 15;
    const int ty = tid >> 4;
    const int rA = tid >> 2;          // 0..63
    const int kA = (tid & 3) << 2;    // 0,4,8,12
    const int kB = tid >> 5;          // 0..7
    const int nB = (tid & 31) << 2;   // 0..124

    const float* Aptr = A + (long long)(bm + rA) * K + kA;
    const float* Bptr = B + (long long)kB * N + bn + nB;
    const long long a64 = (long long)64 * K;
    const long long b8  = (long long)8 * N;

    float acc[8][8];
    #pragma unroll
    for (int i = 0; i < 8; i++)
        #pragma unroll
        for (int j = 0; j < 8; j++) acc[i][j] = 0.f;

    float4 pa0 = *(const float4*)(Aptr);
    float4 pa1 = *(const float4*)(Aptr + a64);
    float4 pb0 = *(const float4*)(Bptr);
    float4 pb1 = *(const float4*)(Bptr + b8);

    for (int k0 = 0; ; k0 += 16) {
        // commit prefetched tile to smem
        As[kA + 0][rA] = pa0.x; As[kA + 1][rA] = pa0.y;
        As[kA + 2][rA] = pa0.z; As[kA + 3][rA] = pa0.w;
        As[kA + 0][rA + 64] = pa1.x; As[kA + 1][rA + 64] = pa1.y;
        As[kA + 2][rA + 64] = pa1.z; As[kA + 3][rA + 64] = pa1.w;
        *(float4*)&Bs[kB][nB]     = pb0;
        *(float4*)&Bs[kB + 8][nB] = pb1;
        __syncthreads();

        const bool more = (k0 + 16) < K;
        if (more) {
            pa0 = *(const float4*)(Aptr + k0 + 16);
            pa1 = *(const float4*)(Aptr + a64 + k0 + 16);
            const long long off = (long long)(k0 + 16) * N;
            pb0 = *(const float4*)(Bptr + off);
            pb1 = *(const float4*)(Bptr + b8 + off);
        }

        #pragma unroll
        for (int kk = 0; kk < 16; kk++) {
            float a[8], b[8];
            *(float4*)&a[0] = *(const float4*)&As[kk][ty << 3];
            *(float4*)&a[4] = *(const float4*)&As[kk][(ty << 3) + 4];
            *(float4*)&b[0] = *(const float4*)&Bs[kk][tx << 3];
            *(float4*)&b[4] = *(const float4*)&Bs[kk][(tx << 3) + 4];
            #pragma unroll
            for (int i = 0; i < 8; i++)
                #pragma unroll
                for (int j = 0; j < 8; j++)
                    acc[i][j] = fmaf(a[i], b[j], acc[i][j]);
        }
        if (!more) break;
        __syncthreads();
    }

    #pragma unroll
    for (int i = 0; i < 8; i++) {
        const long long row = bm + (ty << 3) + i;
        float4 o0 = make_float4(acc[i][0], acc[i][1], acc[i][2], acc[i][3]);
        float4 o1 = make_float4(acc[i][4], acc[i][5], acc[i][6], acc[i][7]);
        *(float4*)&C[row * N + bn + (tx << 3)]     = o0;
        *(float4*)&C[row * N + bn + (tx << 3) + 4] = o1;
    }
}

// ============================================================================
// QK^T (NT GEMM) + scale + mask, writes raw logits to p, per-tile softmax
// stats (rowmax, sum of exp(s - rowmax)) to g_tmax/g_tsum.
// Grid: (ktile=16, qtile=16, b=8). CTA tile 128x128, K=512.
// ============================================================================
__global__ __launch_bounds__(256, 2)
void qk_kernel(const float* __restrict__ mask, float* __restrict__ p)
{
    const int b  = blockIdx.z;
    const int bm = blockIdx.y << 7;   // q rows
    const int bn = blockIdx.x << 7;   // k rows
    const float* A = g_q + (size_t)b * SQ * DQ;
    const float* B = g_k + (size_t)b * SQ * DQ;

    __shared__ float As[16][132];
    __shared__ float Bs[16][132];

    const int tid = threadIdx.x;
    const int tx = tid & 15;
    const int ty = tid >> 4;
    const int rA = tid >> 2;
    const int kA = (tid & 3) << 2;

    const float* Aptr = A + (size_t)(bm + rA) * DQ + kA;
    const float* Bptr = B + (size_t)(bn + rA) * DQ + kA;
    const long long a64 = (long long)64 * DQ;

    float acc[8][8];
    #pragma unroll
    for (int i = 0; i < 8; i++)
        #pragma unroll
        for (int j = 0; j < 8; j++) acc[i][j] = 0.f;

    float4 pa0 = *(const float4*)(Aptr);
    float4 pa1 = *(const float4*)(Aptr + a64);
    float4 pb0 = *(const float4*)(Bptr);
    float4 pb1 = *(const float4*)(Bptr + a64);

    for (int k0 = 0; ; k0 += 16) {
        As[kA + 0][rA] = pa0.x; As[kA + 1][rA] = pa0.y;
        As[kA + 2][rA] = pa0.z; As[kA + 3][rA] = pa0.w;
        As[kA + 0][rA + 64] = pa1.x; As[kA + 1][rA + 64] = pa1.y;
        As[kA + 2][rA + 64] = pa1.z; As[kA + 3][rA + 64] = pa1.w;
        Bs[kA + 0][rA] = pb0.x; Bs[kA + 1][rA] = pb0.y;
        Bs[kA + 2][rA] = pb0.z; Bs[kA + 3][rA] = pb0.w;
        Bs[kA + 0][rA + 64] = pb1.x; Bs[kA + 1][rA + 64] = pb1.y;
        Bs[kA + 2][rA + 64] = pb1.z; Bs[kA + 3][rA + 64] = pb1.w;
        __syncthreads();

        const bool more = (k0 + 16) < DQ;
        if (more) {
            pa0 = *(const float4*)(Aptr + k0 + 16);
            pa1 = *(const float4*)(Aptr + a64 + k0 + 16);
            pb0 = *(const float4*)(Bptr + k0 + 16);
            pb1 = *(const float4*)(Bptr + a64 + k0 + 16);
        }

        #pragma unroll
        for (int kk = 0; kk < 16; kk++) {
            float a[8], bb[8];
            *(float4*)&a[0]  = *(const float4*)&As[kk][ty << 3];
            *(float4*)&a[4]  = *(const float4*)&As[kk][(ty << 3) + 4];
            *(float4*)&bb[0] = *(const float4*)&Bs[kk][tx << 3];
            *(float4*)&bb[4] = *(const float4*)&Bs[kk][(tx << 3) + 4];
            #pragma unroll
            for (int i = 0; i < 8; i++)
                #pragma unroll
                for (int j = 0; j < 8; j++)
                    acc[i][j] = fmaf(a[i], bb[j], acc[i][j]);
        }
        if (!more) break;
        __syncthreads();
    }

    // --- epilogue: scale + mask (rounded like jax: product, then add), stats ---
    const float scale = 0.044194173824159216f;  // 1/sqrt(512)
    #pragma unroll
    for (int i = 0; i < 8; i++) {
        const long long grow = (long long)b * SQ + bm + (ty << 3) + i;
        const float* mrow = mask + grow * SQ + bn + (tx << 3);
        float4 m0 = *(const float4*)mrow;
        float4 m1 = *(const float4*)(mrow + 4);
        float s[8];
        s[0] = __fadd_rn(__fmul_rn(acc[i][0], scale), __fmul_rn(m0.x, -1e9f));
        s[1] = __fadd_rn(__fmul_rn(acc[i][1], scale), __fmul_rn(m0.y, -1e9f));
        s[2] = __fadd_rn(__fmul_rn(acc[i][2], scale), __fmul_rn(m0.z, -1e9f));
        s[3] = __fadd_rn(__fmul_rn(acc[i][3], scale), __fmul_rn(m0.w, -1e9f));
        s[4] = __fadd_rn(__fmul_rn(acc[i][4], scale), __fmul_rn(m1.x, -1e9f));
        s[5] = __fadd_rn(__fmul_rn(acc[i][5], scale), __fmul_rn(m1.y, -1e9f));
        s[6] = __fadd_rn(__fmul_rn(acc[i][6], scale), __fmul_rn(m1.z, -1e9f));
        s[7] = __fadd_rn(__fmul_rn(acc[i][7], scale), __fmul_rn(m1.w, -1e9f));

        float* prow = p + grow * SQ + bn + (tx << 3);
        *(float4*)prow       = make_float4(s[0], s[1], s[2], s[3]);
        *(float4*)(prow + 4) = make_float4(s[4], s[5], s[6], s[7]);

        float mx = s[0];
        #pragma unroll
        for (int j = 1; j < 8; j++) mx = fmaxf(mx, s[j]);
        #pragma unroll
        for (int off = 1; off < 16; off <<= 1)
            mx = fmaxf(mx, __shfl_xor_sync(0xffffffffu, mx, off));

        float es = 0.f;
        #pragma unroll
        for (int j = 0; j < 8; j++) es += __expf(s[j] - mx);
        #pragma unroll
        for (int off = 1; off < 16; off <<= 1)
            es += __shfl_xor_sync(0xffffffffu, es, off);

        if (tx == 0) {
            g_tmax[grow * 16 + blockIdx.x] = mx;
            g_tsum[grow * 16 + blockIdx.x] = es;
        }
    }
}

// ============================================================================
// Per-row softmax normalize: combine 16 tile stats -> m, 1/l; p = exp(s-m)/l.
// Grid: 16384 CTAs x 256 threads.
// ============================================================================
__global__ __launch_bounds__(256)
void softmax_norm_kernel(float* __restrict__ p)
{
    const int g = blockIdx.x;
    __shared__ float sh[2];
    if (threadIdx.x == 0) {
        float m = __int_as_float(0xff800000);  // -inf
        #pragma unroll
        for (int t = 0; t < 16; t++) m = fmaxf(m, g_tmax[g * 16 + t]);
        float l = 0.f;
        #pragma unroll
        for (int t = 0; t < 16; t++)
            l += g_tsum[g * 16 + t] * __expf(g_tmax[g * 16 + t] - m);
        sh[0] = m;
        sh[1] = 1.f / l;
    }
    __syncthreads();
    const float m = sh[0], inv = sh[1];
    float* row = p + (size_t)g * SQ;
    #pragma unroll
    for (int it = 0; it < 2; it++) {
        const int i = (threadIdx.x << 2) + (it << 10);
        float4 v = *(float4*)&row[i];
        v.x = __expf(v.x - m) * inv;
        v.y = __expf(v.y - m) * inv;
        v.z = __expf(v.z - m) * inv;
        v.w = __expf(v.w - m) * inv;
        *(float4*)&row[i] = v;
    }
}

// ============================================================================
// Host launcher (graph-capturable: kernel launches only)
// ============================================================================
extern "C" void kernel_launch(void* const* d_in, const int* in_sizes, int n_in,
                              void* d_out, int out_size)
{
    const float* qx   = (const float*)d_in[0];
    const float* kx   = (const float*)d_in[1];
    const float* vx   = (const float*)d_in[2];
    const float* mask = (const float*)d_in[3];
    const float* Wq   = (const float*)d_in[4];
    const float* Wk   = (const float*)d_in[5];
    const float* Wv   = (const float*)d_in[6];

    float* h = (float*)d_out;                       // [8,2048,512]
    float* p = h + (size_t)MROWS * DQ;              // [8,2048,2048]

    float *gq, *gk, *gv;
    cudaGetSymbolAddress((void**)&gq, g_q);
    cudaGetSymbolAddress((void**)&gk, g_k);
    cudaGetSymbolAddress((void**)&gv, g_v);

    dim3 blk(256);

    // projections: [16384,512] = X[16384,512] @ W[512,512]
    gemm_nn_kernel<<<dim3(4, 128, 1), blk>>>(qx, Wq, gq, MROWS, DQ, DQ, 0, 0, 0);
    gemm_nn_kernel<<<dim3(4, 128, 1), blk>>>(kx, Wk, gk, MROWS, DQ, DQ, 0, 0, 0);
    gemm_nn_kernel<<<dim3(4, 128, 1), blk>>>(vx, Wv, gv, MROWS, DQ, DQ, 0, 0, 0);

    // logits + mask + tile softmax stats
    qk_kernel<<<dim3(16, 16, NBATCH), blk>>>(mask, p);

    // normalize p in place
    softmax_norm_kernel<<<dim3(MROWS), blk>>>(p);

    // h = p @ v  (batched over z)
    gemm_nn_kernel<<<dim3(4, 16, NBATCH), blk>>>(
        p, gv, h, SQ, DQ, SQ,
        (long long)SQ * SQ, (long long)SQ * DQ, (long long)SQ * DQ);
}

// round 5
// speedup vs baseline: 1.9863x; 1.9863x over previous
#include <cuda_runtime.h>
#include <cuda_bf16.h>
#include <cstdint>
#include <math.h>

#define SQ 2048
#define DQ 512
#define NB 8
#define MR (NB*SQ)   // 16384

// ============================================================================
// Scratch (device globals — allocation-free)
// ============================================================================
struct Scratch {
    __nv_bfloat16 qhi[(size_t)MR * DQ], qlo[(size_t)MR * DQ];
    __nv_bfloat16 khi[(size_t)MR * DQ], klo[(size_t)MR * DQ];
    __nv_bfloat16 vthi[(size_t)DQ * MR], vtlo[(size_t)DQ * MR];   // v transposed [d][s]
    __nv_bfloat16 wthi[3][DQ * DQ], wtlo[3][DQ * DQ];             // W transposed [d][f]
    float tmax[MR * 16], tsum[MR * 16];
};
__device__ Scratch g_s;

// ============================================================================
// PTX helpers (base-target only: ldmatrix + mma.sync, sm_75/80+ features)
// ============================================================================
__device__ __forceinline__ uint32_t smem_u32(const void* p) {
    uint32_t a;
    asm("{ .reg .u64 t; cvta.to.shared.u64 t, %1; cvt.u32.u64 %0, t; }" : "=r"(a) : "l"(p));
    return a;
}
__device__ __forceinline__ void ldsm4(uint32_t* r, uint32_t addr) {
    asm volatile("ldmatrix.sync.aligned.m8n8.x4.shared.b16 {%0,%1,%2,%3}, [%4];"
        : "=r"(r[0]), "=r"(r[1]), "=r"(r[2]), "=r"(r[3]) : "r"(addr));
}
__device__ __forceinline__ void ldsm2(uint32_t* r, uint32_t addr) {
    asm volatile("ldmatrix.sync.aligned.m8n8.x2.shared.b16 {%0,%1}, [%2];"
        : "=r"(r[0]), "=r"(r[1]) : "r"(addr));
}
__device__ __forceinline__ void mma16816(float* c, const uint32_t* a, const uint32_t* b) {
    asm volatile(
        "mma.sync.aligned.m16n8k16.row.col.f32.bf16.bf16.f32 "
        "{%0,%1,%2,%3}, {%4,%5,%6,%7}, {%8,%9}, {%0,%1,%2,%3};"
        : "+f"(c[0]), "+f"(c[1]), "+f"(c[2]), "+f"(c[3])
        : "r"(a[0]), "r"(a[1]), "r"(a[2]), "r"(a[3]), "r"(b[0]), "r"(b[1]));
}

// bf16 split helpers
__device__ __forceinline__ void split2(float x, float y, uint32_t& hi, uint32_t& lo) {
    union { __nv_bfloat16 b[2]; uint32_t u; } H, L;
    H.b[0] = __float2bfloat16(x); H.b[1] = __float2bfloat16(y);
    L.b[0] = __float2bfloat16(x - __bfloat162float(H.b[0]));
    L.b[1] = __float2bfloat16(y - __bfloat162float(H.b[1]));
    hi = H.u; lo = L.u;
}

// ============================================================================
// SMEM layout: per stage (stride 40960B): Ahi@0, Alo@10240, Bhi@20480, Blo@30720.
// Tile rows are 32 bf16 (64B) padded to 80B stride (20-bank walk: conflict-free
// for 8-row ldmatrix gathers and OK for stores). Stats at 81920 (4KB).
// ============================================================================
#define STG_STR  40960
#define OFF_ALO  10240
#define OFF_BHI  20480
#define OFF_BLO  30720
#define SM_STATS 81920
#define SM_TOTAL 86016
#define RSTRIDE  80

// ============================================================================
// Unified tensor GEMM: C(128x128 tile) = A[M,K] * B[N,K]^T, K-major operands,
// via 3-pass split-bf16 mma.sync (hh + hl + lh).
// AMODE: 0 = A fp32 (split on the fly), 1 = A bf16 pre-split pair.
// EPI:   0 = q/k proj: store hi/lo bf16 [row*512+col]
//        1 = v proj:   store hi/lo bf16 transposed [col*MR+row]
//        2 = QK: scale+mask -> raw logits in p + per-tile softmax stats
//        3 = PV: store fp32 h [grow*512+col]
// ============================================================================
template<int AMODE, int EPI>
__global__ __launch_bounds__(256)
void mma_gemm(const float* __restrict__ Af,
              const __nv_bfloat16* __restrict__ Ah, const __nv_bfloat16* __restrict__ Al,
              const __nv_bfloat16* __restrict__ Bh, const __nv_bfloat16* __restrict__ Bl,
              int lda, int ldb, int K,
              long long aBatch, long long bBatch,
              float* __restrict__ outF,
              __nv_bfloat16* __restrict__ Oh, __nv_bfloat16* __restrict__ Ol,
              const float* __restrict__ mask)
{
    extern __shared__ char smem[];
    const uint32_t sbu = smem_u32(smem);
    const int tid = threadIdx.x;
    const int lane = tid & 31, wid = tid >> 5;
    const int wm = wid >> 2, wn = wid & 3;         // 2 x 4 warp grid, tile 64x32
    const int bm = blockIdx.y << 7, bn = blockIdx.x << 7;
    const long long aOff = (long long)blockIdx.z * aBatch;
    const long long bOff = (long long)blockIdx.z * bBatch;

    float c[4][4][4];
    #pragma unroll
    for (int i = 0; i < 4; i++)
        #pragma unroll
        for (int j = 0; j < 4; j++)
            { c[i][j][0]=0.f; c[i][j][1]=0.f; c[i][j][2]=0.f; c[i][j][3]=0.f; }

    const int nchunks = K >> 5;

    // ---- prefetch registers ----
    float4 pa[4];                 // AMODE 0: A fp32, 128x32 chunk
    uint4 pah[2], pal[2];         // AMODE 1: A bf16 pair
    uint4 pbh[2], pbl[2];         // B bf16 pair

    // loader indices
    const int a0_kq = tid & 7,  a0_r = tid >> 3;   // fp32: 4-float col groups, 32 rows
    const int p_kq  = tid & 3,  p_r  = tid >> 2;   // pair: 8-bf16 col groups, 64 rows

    // ldmatrix lane address pieces
    const int laneRowA = (lane & 7) + ((lane >> 3) & 1) * 8;
    const int laneColA = ((lane >> 4) & 1) * 16;
    const int laneRowB = lane & 7;
    const int laneColB = ((lane >> 3) & 1) * 16;

    #define PREFETCH(CH) do { \
        const int k0 = (CH) << 5; \
        if (AMODE == 0) { \
            _Pragma("unroll") \
            for (int i = 0; i < 4; i++) \
                pa[i] = *(const float4*)(Af + aOff + (long long)(bm + a0_r + 32*i) * lda + k0 + a0_kq*4); \
        } else { \
            _Pragma("unroll") \
            for (int i = 0; i < 2; i++) { \
                const long long g = aOff + (long long)(bm + p_r + 64*i) * lda + k0 + p_kq*8; \
                pah[i] = *(const uint4*)(Ah + g); \
                pal[i] = *(const uint4*)(Al + g); \
            } \
        } \
        _Pragma("unroll") \
        for (int i = 0; i < 2; i++) { \
            const long long g = bOff + (long long)(bn + p_r + 64*i) * ldb + k0 + p_kq*8; \
            pbh[i] = *(const uint4*)(Bh + g); \
            pbl[i] = *(const uint4*)(Bl + g); \
        } \
    } while (0)

    PREFETCH(0);

    for (int ch = 0; ch < nchunks; ch++) {
        char* st = smem + (ch & 1) * STG_STR;
        // ---- commit prefetched chunk to smem ----
        if (AMODE == 0) {
            #pragma unroll
            for (int i = 0; i < 4; i++) {
                const int row = a0_r + 32*i;
                uint32_t h0, l0, h1, l1;
                split2(pa[i].x, pa[i].y, h0, l0);
                split2(pa[i].z, pa[i].w, h1, l1);
                uint32_t* dh = (uint32_t*)(st + row*RSTRIDE + a0_kq*8);
                uint32_t* dl = (uint32_t*)(st + OFF_ALO + row*RSTRIDE + a0_kq*8);
                dh[0] = h0; dh[1] = h1;
                dl[0] = l0; dl[1] = l1;
            }
        } else {
            #pragma unroll
            for (int i = 0; i < 2; i++) {
                const int row = p_r + 64*i;
                *(uint4*)(st + row*RSTRIDE + p_kq*16)           = pah[i];
                *(uint4*)(st + OFF_ALO + row*RSTRIDE + p_kq*16) = pal[i];
            }
        }
        #pragma unroll
        for (int i = 0; i < 2; i++) {
            const int row = p_r + 64*i;
            *(uint4*)(st + OFF_BHI + row*RSTRIDE + p_kq*16) = pbh[i];
            *(uint4*)(st + OFF_BLO + row*RSTRIDE + p_kq*16) = pbl[i];
        }
        __syncthreads();

        if (ch + 1 < nchunks) PREFETCH(ch + 1);

        // ---- compute chunk from smem ----
        const uint32_t sb = sbu + (ch & 1) * STG_STR;
        #pragma unroll
        for (int h = 0; h < 2; h++) {
            uint32_t ah[4][4], al[4][4];
            #pragma unroll
            for (int mt = 0; mt < 4; mt++) {
                const uint32_t ra = (wm*64 + mt*16 + laneRowA) * RSTRIDE + h*32 + laneColA;
                ldsm4(ah[mt], sb + ra);
                ldsm4(al[mt], sb + OFF_ALO + ra);
            }
            #pragma unroll
            for (int nt = 0; nt < 4; nt++) {
                const uint32_t rb = (wn*32 + nt*8 + laneRowB) * RSTRIDE + h*32 + laneColB;
                uint32_t bh2[2], bl2[2];
                ldsm2(bh2, sb + OFF_BHI + rb);
                ldsm2(bl2, sb + OFF_BLO + rb);
                #pragma unroll
                for (int mt = 0; mt < 4; mt++) mma16816(c[mt][nt], ah[mt], bh2);
                #pragma unroll
                for (int mt = 0; mt < 4; mt++) mma16816(c[mt][nt], ah[mt], bl2);
                #pragma unroll
                for (int mt = 0; mt < 4; mt++) mma16816(c[mt][nt], al[mt], bh2);
            }
        }
    }

    // ======================= epilogues =======================
    const int qrow = lane >> 2;          // 0..7
    const int qcol = (lane & 3) * 2;     // 0,2,4,6

    if (EPI == 0) {
        #pragma unroll
        for (int mt = 0; mt < 4; mt++)
            #pragma unroll
            for (int i = 0; i < 2; i++) {
                const long long row = bm + wm*64 + mt*16 + qrow + i*8;
                #pragma unroll
                for (int nt = 0; nt < 4; nt++) {
                    const int col = bn + wn*32 + nt*8 + qcol;
                    uint32_t hh, ll;
                    split2(c[mt][nt][2*i], c[mt][nt][2*i+1], hh, ll);
                    *(uint32_t*)(Oh + row*DQ + col) = hh;
                    *(uint32_t*)(Ol + row*DQ + col) = ll;
                }
            }
    } else if (EPI == 1) {
        #pragma unroll
        for (int mt = 0; mt < 4; mt++)
            #pragma unroll
            for (int i = 0; i < 2; i++) {
                const long long row = bm + wm*64 + mt*16 + qrow + i*8;
                #pragma unroll
                for (int nt = 0; nt < 4; nt++)
                    #pragma unroll
                    for (int j = 0; j < 2; j++) {
                        const long long colg = bn + wn*32 + nt*8 + qcol + j;
                        const float f = c[mt][nt][2*i+j];
                        const __nv_bfloat16 hh = __float2bfloat16(f);
                        Oh[colg*MR + row] = hh;
                        Ol[colg*MR + row] = __float2bfloat16(f - __bfloat162float(hh));
                    }
            }
    } else if (EPI == 2) {
        const float scale = 0.044194173824159216f;  // 1/sqrt(512)
        float* smax = (float*)(smem + SM_STATS);    // [4][128]
        float* ssum = smax + 512;
        #pragma unroll
        for (int mt = 0; mt < 4; mt++)
            #pragma unroll
            for (int i = 0; i < 2; i++) {
                const int rowLocal = wm*64 + mt*16 + qrow + i*8;
                const long long grow = (long long)blockIdx.z * SQ + bm + rowLocal;
                float s[8];
                #pragma unroll
                for (int nt = 0; nt < 4; nt++) {
                    const int col = bn + wn*32 + nt*8 + qcol;
                    const float2 m = *(const float2*)(mask + grow*SQ + col);
                    s[2*nt]   = __fadd_rn(__fmul_rn(c[mt][nt][2*i],   scale), __fmul_rn(m.x, -1e9f));
                    s[2*nt+1] = __fadd_rn(__fmul_rn(c[mt][nt][2*i+1], scale), __fmul_rn(m.y, -1e9f));
                    *(float2*)(outF + grow*SQ + col) = make_float2(s[2*nt], s[2*nt+1]);
                }
                float mx = s[0];
                #pragma unroll
                for (int j = 1; j < 8; j++) mx = fmaxf(mx, s[j]);
                mx = fmaxf(mx, __shfl_xor_sync(0xffffffffu, mx, 1));
                mx = fmaxf(mx, __shfl_xor_sync(0xffffffffu, mx, 2));
                float es = 0.f;
                #pragma unroll
                for (int j = 0; j < 8; j++) es += __expf(s[j] - mx);
                es += __shfl_xor_sync(0xffffffffu, es, 1);
                es += __shfl_xor_sync(0xffffffffu, es, 2);
                if ((lane & 3) == 0) {
                    smax[wn*128 + rowLocal] = mx;
                    ssum[wn*128 + rowLocal] = es;
                }
            }
        __syncthreads();
        if (tid < 128) {
            float m = smax[tid];
            #pragma unroll
            for (int w = 1; w < 4; w++) m = fmaxf(m, smax[w*128 + tid]);
            float l = 0.f;
            #pragma unroll
            for (int w = 0; w < 4; w++)
                l += ssum[w*128 + tid] * __expf(smax[w*128 + tid] - m);
            const long long grow = (long long)blockIdx.z * SQ + bm + tid;
            g_s.tmax[grow*16 + blockIdx.x] = m;
            g_s.tsum[grow*16 + blockIdx.x] = l;
        }
    } else {  // EPI == 3
        #pragma unroll
        for (int mt = 0; mt < 4; mt++)
            #pragma unroll
            for (int i = 0; i < 2; i++) {
                const long long grow = (long long)blockIdx.z * SQ + bm + wm*64 + mt*16 + qrow + i*8;
                #pragma unroll
                for (int nt = 0; nt < 4; nt++) {
                    const int col = bn + wn*32 + nt*8 + qcol;
                    *(float2*)(outF + grow*DQ + col) =
                        make_float2(c[mt][nt][2*i], c[mt][nt][2*i+1]);
                }
            }
    }
    #undef PREFETCH
}

// ============================================================================
// Weight transpose + split: Wt[d][f] = split(W[f][d])
// ============================================================================
__global__ __launch_bounds__(256)
void wt_split(const float* __restrict__ W, __nv_bfloat16* __restrict__ Th,
              __nv_bfloat16* __restrict__ Tl)
{
    const int e = blockIdx.x * 256 + threadIdx.x;
    const int f = e >> 9, dd = e & 511;
    float v = W[f * DQ + dd];
    __nv_bfloat16 h = __float2bfloat16(v);
    Th[dd * DQ + f] = h;
    Tl[dd * DQ + f] = __float2bfloat16(v - __bfloat162float(h));
}

// ============================================================================
// Per-row softmax normalize: combine 16 tile stats -> m, 1/l; p = exp(s-m)/l.
// ============================================================================
__global__ __launch_bounds__(256)
void softmax_norm_kernel(float* __restrict__ p)
{
    const int g = blockIdx.x;
    __shared__ float sh[2];
    if (threadIdx.x == 0) {
        float m = __int_as_float(0xff800000);
        #pragma unroll
        for (int t = 0; t < 16; t++) m = fmaxf(m, g_s.tmax[g * 16 + t]);
        float l = 0.f;
        #pragma unroll
        for (int t = 0; t < 16; t++)
            l += g_s.tsum[g * 16 + t] * __expf(g_s.tmax[g * 16 + t] - m);
        sh[0] = m;
        sh[1] = 1.f / l;
    }
    __syncthreads();
    const float m = sh[0], inv = sh[1];
    float* row = p + (size_t)g * SQ;
    #pragma unroll
    for (int it = 0; it < 2; it++) {
        const int i = (threadIdx.x << 2) + (it << 10);
        float4 v = *(float4*)&row[i];
        v.x = __expf(v.x - m) * inv;
        v.y = __expf(v.y - m) * inv;
        v.z = __expf(v.z - m) * inv;
        v.w = __expf(v.w - m) * inv;
        *(float4*)&row[i] = v;
    }
}

// ============================================================================
// Host launcher (graph-capturable: kernel launches only)
// ============================================================================
extern "C" void kernel_launch(void* const* d_in, const int* in_sizes, int n_in,
                              void* d_out, int out_size)
{
    const float* qx   = (const float*)d_in[0];
    const float* kx   = (const float*)d_in[1];
    const float* vx   = (const float*)d_in[2];
    const float* mask = (const float*)d_in[3];
    const float* Wq   = (const float*)d_in[4];
    const float* Wk   = (const float*)d_in[5];
    const float* Wv   = (const float*)d_in[6];

    float* h = (float*)d_out;                  // [8,2048,512]
    float* p = h + (size_t)MR * DQ;            // [8,2048,2048]

    void* sbase = nullptr;
    cudaGetSymbolAddress(&sbase, g_s);
    Scratch* S = (Scratch*)sbase;

    static bool attr_done = false;
    if (!attr_done) {
        cudaFuncSetAttribute(mma_gemm<0,0>, cudaFuncAttributeMaxDynamicSharedMemorySize, SM_TOTAL);
        cudaFuncSetAttribute(mma_gemm<0,1>, cudaFuncAttributeMaxDynamicSharedMemorySize, SM_TOTAL);
        cudaFuncSetAttribute(mma_gemm<1,2>, cudaFuncAttributeMaxDynamicSharedMemorySize, SM_TOTAL);
        cudaFuncSetAttribute(mma_gemm<0,3>, cudaFuncAttributeMaxDynamicSharedMemorySize, SM_TOTAL);
        attr_done = true;
    }

    // 1) transpose+split weights
    wt_split<<<1024, 256>>>(Wq, S->wthi[0], S->wtlo[0]);
    wt_split<<<1024, 256>>>(Wk, S->wthi[1], S->wtlo[1]);
    wt_split<<<1024, 256>>>(Wv, S->wthi[2], S->wtlo[2]);

    // 2) projections: q,k -> pre-split bf16; v -> transposed pre-split
    mma_gemm<0,0><<<dim3(4, 128, 1), 256, SM_TOTAL>>>(
        qx, nullptr, nullptr, S->wthi[0], S->wtlo[0],
        DQ, DQ, DQ, 0, 0, nullptr, S->qhi, S->qlo, nullptr);
    mma_gemm<0,0><<<dim3(4, 128, 1), 256, SM_TOTAL>>>(
        kx, nullptr, nullptr, S->wthi[1], S->wtlo[1],
        DQ, DQ, DQ, 0, 0, nullptr, S->khi, S->klo, nullptr);
    mma_gemm<0,1><<<dim3(4, 128, 1), 256, SM_TOTAL>>>(
        vx, nullptr, nullptr, S->wthi[2], S->wtlo[2],
        DQ, DQ, DQ, 0, 0, nullptr, S->vthi, S->vtlo, nullptr);

    // 3) QK^T + scale + mask + tile softmax stats -> raw logits in p
    mma_gemm<1,2><<<dim3(16, 16, NB), 256, SM_TOTAL>>>(
        nullptr, S->qhi, S->qlo, S->khi, S->klo,
        DQ, DQ, DQ, (long long)SQ * DQ, (long long)SQ * DQ,
        p, nullptr, nullptr, mask);

    // 4) normalize p in place
    softmax_norm_kernel<<<dim3(MR), 256>>>(p);

    // 5) h = p @ v  (A = p fp32 split on the fly, B = v^T pre-split)
    mma_gemm<0,3><<<dim3(4, 16, NB), 256, SM_TOTAL>>>(
        p, nullptr, nullptr, S->vthi, S->vtlo,
        SQ, MR, SQ, (long long)SQ * SQ, (long long)SQ,
        h, nullptr, nullptr, nullptr);
}

// round 6
// speedup vs baseline: 2.0316x; 1.0228x over previous
#include <cuda_runtime.h>
#include <cuda_bf16.h>
#include <cstdint>
#include <math.h>

#define SQ 2048
#define DQ 512
#define NB 8
#define MR (NB*SQ)   // 16384

// ============================================================================
// Scratch (device globals — allocation-free)
// ============================================================================
struct Scratch {
    __nv_bfloat16 xhi[3][(size_t)MR * DQ], xlo[3][(size_t)MR * DQ];   // split inputs
    __nv_bfloat16 qhi[(size_t)MR * DQ], qlo[(size_t)MR * DQ];
    __nv_bfloat16 khi[(size_t)MR * DQ], klo[(size_t)MR * DQ];
    __nv_bfloat16 vthi[(size_t)DQ * MR], vtlo[(size_t)DQ * MR];       // v transposed [d][s]
    __nv_bfloat16 wthi[3][DQ * DQ], wtlo[3][DQ * DQ];                 // W transposed [d][f]
    __nv_bfloat16 phi[(size_t)MR * SQ], plo[(size_t)MR * SQ];         // split normalized p
    float tmax[MR * 16], tsum[MR * 16];
};
__device__ Scratch g_s;

// ============================================================================
// PTX helpers (base-target features only: cp.async, ldmatrix, mma.sync)
// ============================================================================
__device__ __forceinline__ uint32_t smem_u32(const void* p) {
    uint32_t a;
    asm("{ .reg .u64 t; cvta.to.shared.u64 t, %1; cvt.u32.u64 %0, t; }" : "=r"(a) : "l"(p));
    return a;
}
__device__ __forceinline__ void cpa16(uint32_t dst, const void* src) {
    asm volatile("cp.async.cg.shared.global [%0], [%1], 16;" :: "r"(dst), "l"(src));
}
__device__ __forceinline__ void ldsm4(uint32_t* r, uint32_t addr) {
    asm volatile("ldmatrix.sync.aligned.m8n8.x4.shared.b16 {%0,%1,%2,%3}, [%4];"
        : "=r"(r[0]), "=r"(r[1]), "=r"(r[2]), "=r"(r[3]) : "r"(addr));
}
__device__ __forceinline__ void ldsm2(uint32_t* r, uint32_t addr) {
    asm volatile("ldmatrix.sync.aligned.m8n8.x2.shared.b16 {%0,%1}, [%2];"
        : "=r"(r[0]), "=r"(r[1]) : "r"(addr));
}
__device__ __forceinline__ void mma16816(float* c, const uint32_t* a, const uint32_t* b) {
    asm volatile(
        "mma.sync.aligned.m16n8k16.row.col.f32.bf16.bf16.f32 "
        "{%0,%1,%2,%3}, {%4,%5,%6,%7}, {%8,%9}, {%0,%1,%2,%3};"
        : "+f"(c[0]), "+f"(c[1]), "+f"(c[2]), "+f"(c[3])
        : "r"(a[0]), "r"(a[1]), "r"(a[2]), "r"(a[3]), "r"(b[0]), "r"(b[1]));
}
__device__ __forceinline__ void split2(float x, float y, uint32_t& hi, uint32_t& lo) {
    union { __nv_bfloat16 b[2]; uint32_t u; } H, L;
    H.b[0] = __float2bfloat16(x); H.b[1] = __float2bfloat16(y);
    L.b[0] = __float2bfloat16(x - __bfloat162float(H.b[0]));
    L.b[1] = __float2bfloat16(y - __bfloat162float(H.b[1]));
    hi = H.u; lo = L.u;
}

// ============================================================================
// SMEM: per stage (40960B): Ahi@0, Alo@10240, Bhi@20480, Blo@30720.
// Rows = 32 bf16 (64B) at 80B stride (16B-aligned, 20-bank walk). 2 stages.
// Stats region at 81920 (4KB).  Total 86016B -> 2 CTAs/SM.
// ============================================================================
#define STG_STR  40960
#define OFF_ALO  10240
#define OFF_BHI  20480
#define OFF_BLO  30720
#define SM_STATS 81920
#define SM_TOTAL 86016
#define RSTRIDE  80

// ---- cp.async one K=32 chunk of all 4 tiles (2 threads/row, 2x16B each) ----
__device__ __forceinline__ void load_chunk(
    uint32_t sbu, int stg, int tid,
    const __nv_bfloat16* Ah, const __nv_bfloat16* Al,
    const __nv_bfloat16* Bh, const __nv_bfloat16* Bl,
    long long aBase, long long bBase, int lda, int ldb, int k0)
{
    const int lrow = tid >> 1;
    const int seg  = (tid & 1) * 16;                 // element offset within chunk
    const uint32_t sd = sbu + stg * STG_STR + lrow * RSTRIDE + seg * 2;
    const long long ga = aBase + (long long)lrow * lda + k0 + seg;
    const long long gb = bBase + (long long)lrow * ldb + k0 + seg;
    cpa16(sd,                Ah + ga); cpa16(sd + 16,                Ah + ga + 8);
    cpa16(sd + OFF_ALO,      Al + ga); cpa16(sd + OFF_ALO + 16,      Al + ga + 8);
    cpa16(sd + OFF_BHI,      Bh + gb); cpa16(sd + OFF_BHI + 16,      Bh + gb + 8);
    cpa16(sd + OFF_BLO,      Bl + gb); cpa16(sd + OFF_BLO + 16,      Bl + gb + 8);
    asm volatile("cp.async.commit_group;");
}

// ---- 3-pass split-bf16 mainloop: C(128x128) += A[128,K] * B[128,K]^T ----
__device__ __forceinline__ void gemm_mainloop(
    uint32_t sbu, int tid, int lane, int wm, int wn,
    const __nv_bfloat16* Ah, const __nv_bfloat16* Al,
    const __nv_bfloat16* Bh, const __nv_bfloat16* Bl,
    long long aBase, long long bBase, int lda, int ldb, int nchunks,
    float c[4][4][4])
{
    const int laneRowA = (lane & 7) + ((lane >> 3) & 1) * 8;
    const int laneColA = ((lane >> 4) & 1) * 16;
    const int laneRowB = lane & 7;
    const int laneColB = ((lane >> 3) & 1) * 16;

    load_chunk(sbu, 0, tid, Ah, Al, Bh, Bl, aBase, bBase, lda, ldb, 0);
    load_chunk(sbu, 1, tid, Ah, Al, Bh, Bl, aBase, bBase, lda, ldb, 32);

    for (int ch = 0; ch < nchunks; ch++) {
        asm volatile("cp.async.wait_group 1;");
        __syncthreads();

        const uint32_t sb = sbu + (ch & 1) * STG_STR;
        #pragma unroll
        for (int h = 0; h < 2; h++) {
            uint32_t bh[4][2], bl[4][2];
            #pragma unroll
            for (int nt = 0; nt < 4; nt++) {
                const uint32_t rb = (wn*32 + nt*8 + laneRowB) * RSTRIDE + h*32 + laneColB;
                ldsm2(bh[nt], sb + OFF_BHI + rb);
                ldsm2(bl[nt], sb + OFF_BLO + rb);
            }
            #pragma unroll
            for (int mt = 0; mt < 4; mt++) {
                uint32_t ah[4], al[4];
                const uint32_t ra = (wm*64 + mt*16 + laneRowA) * RSTRIDE + h*32 + laneColA;
                ldsm4(ah, sb + ra);
                ldsm4(al, sb + OFF_ALO + ra);
                #pragma unroll
                for (int nt = 0; nt < 4; nt++) {
                    mma16816(c[mt][nt], ah, bh[nt]);
                    mma16816(c[mt][nt], ah, bl[nt]);
                    mma16816(c[mt][nt], al, bh[nt]);
                }
            }
        }
        __syncthreads();
        if (ch + 2 < nchunks)
            load_chunk(sbu, ch & 1, tid, Ah, Al, Bh, Bl, aBase, bBase, lda, ldb, (ch + 2) << 5);
        else
            asm volatile("cp.async.commit_group;");   // keep group count in lockstep
    }
}

// ---- epilogue: store pre-split bf16 pair, row-major [row*DQ+col] ----
__device__ __forceinline__ void epi_pair(float c[4][4][4], int lane, int wm, int wn,
    long long bm, int bn, __nv_bfloat16* Oh, __nv_bfloat16* Ol)
{
    const int qrow = lane >> 2, qcol = (lane & 3) * 2;
    #pragma unroll
    for (int mt = 0; mt < 4; mt++)
        #pragma unroll
        for (int i = 0; i < 2; i++) {
            const long long row = bm + wm*64 + mt*16 + qrow + i*8;
            #pragma unroll
            for (int nt = 0; nt < 4; nt++) {
                const int col = bn + wn*32 + nt*8 + qcol;
                uint32_t hh, ll;
                split2(c[mt][nt][2*i], c[mt][nt][2*i+1], hh, ll);
                *(uint32_t*)(Oh + row*DQ + col) = hh;
                *(uint32_t*)(Ol + row*DQ + col) = ll;
            }
        }
}

// ---- epilogue: store pre-split bf16 pair transposed [col*MR + row] ----
__device__ __forceinline__ void epi_pairT(float c[4][4][4], int lane, int wm, int wn,
    long long bm, int bn, __nv_bfloat16* Oh, __nv_bfloat16* Ol)
{
    const int qrow = lane >> 2, qcol = (lane & 3) * 2;
    #pragma unroll
    for (int mt = 0; mt < 4; mt++)
        #pragma unroll
        for (int i = 0; i < 2; i++) {
            const long long row = bm + wm*64 + mt*16 + qrow + i*8;
            #pragma unroll
            for (int nt = 0; nt < 4; nt++)
                #pragma unroll
                for (int j = 0; j < 2; j++) {
                    const long long colg = bn + wn*32 + nt*8 + qcol + j;
                    const float f = c[mt][nt][2*i+j];
                    const __nv_bfloat16 hh = __float2bfloat16(f);
                    Oh[colg*MR + row] = hh;
                    Ol[colg*MR + row] = __float2bfloat16(f - __bfloat162float(hh));
                }
        }
}

// ============================================================================
// Fused projection kernel: z=0 -> q (pair), z=1 -> k (pair), z=2 -> v (pair^T)
// ============================================================================
__global__ __launch_bounds__(256, 2)
void proj_gemm()
{
    extern __shared__ char smem[];
    const uint32_t sbu = smem_u32(smem);
    const int tid = threadIdx.x, lane = tid & 31, wid = tid >> 5;
    const int wm = wid >> 2, wn = wid & 3;
    const int bm = blockIdx.y << 7, bn = blockIdx.x << 7;
    const int z = blockIdx.z;

    float c[4][4][4];
    #pragma unroll
    for (int i = 0; i < 4; i++)
        #pragma unroll
        for (int j = 0; j < 4; j++)
            { c[i][j][0]=0.f; c[i][j][1]=0.f; c[i][j][2]=0.f; c[i][j][3]=0.f; }

    gemm_mainloop(sbu, tid, lane, wm, wn,
                  g_s.xhi[z], g_s.xlo[z], g_s.wthi[z], g_s.wtlo[z],
                  (long long)bm * DQ, (long long)bn * DQ, DQ, DQ, DQ >> 5, c);

    if (z == 0)      epi_pair (c, lane, wm, wn, bm, bn, g_s.qhi, g_s.qlo);
    else if (z == 1) epi_pair (c, lane, wm, wn, bm, bn, g_s.khi, g_s.klo);
    else             epi_pairT(c, lane, wm, wn, bm, bn, g_s.vthi, g_s.vtlo);
}

// ============================================================================
// QK kernel: raw logits (scale+mask, jax rounding) -> p, per-tile stats
// ============================================================================
__global__ __launch_bounds__(256, 2)
void qk_gemm(float* __restrict__ outF, const float* __restrict__ mask)
{
    extern __shared__ char smem[];
    const uint32_t sbu = smem_u32(smem);
    const int tid = threadIdx.x, lane = tid & 31, wid = tid >> 5;
    const int wm = wid >> 2, wn = wid & 3;
    const int bm = blockIdx.y << 7, bn = blockIdx.x << 7;
    const long long zOff = (long long)blockIdx.z * SQ * DQ;

    float c[4][4][4];
    #pragma unroll
    for (int i = 0; i < 4; i++)
        #pragma unroll
        for (int j = 0; j < 4; j++)
            { c[i][j][0]=0.f; c[i][j][1]=0.f; c[i][j][2]=0.f; c[i][j][3]=0.f; }

    gemm_mainloop(sbu, tid, lane, wm, wn,
                  g_s.qhi, g_s.qlo, g_s.khi, g_s.klo,
                  zOff + (long long)bm * DQ, zOff + (long long)bn * DQ,
                  DQ, DQ, DQ >> 5, c);

    const float scale = 0.044194173824159216f;  // 1/sqrt(512)
    const int qrow = lane >> 2, qcol = (lane & 3) * 2;
    float* smax = (float*)(smem + SM_STATS);    // [4][128]
    float* ssum = smax + 512;
    #pragma unroll
    for (int mt = 0; mt < 4; mt++)
        #pragma unroll
        for (int i = 0; i < 2; i++) {
            const int rowLocal = wm*64 + mt*16 + qrow + i*8;
            const long long grow = (long long)blockIdx.z * SQ + bm + rowLocal;
            float s[8];
            #pragma unroll
            for (int nt = 0; nt < 4; nt++) {
                const int col = bn + wn*32 + nt*8 + qcol;
                const float2 m = *(const float2*)(mask + grow*SQ + col);
                s[2*nt]   = __fadd_rn(__fmul_rn(c[mt][nt][2*i],   scale), __fmul_rn(m.x, -1e9f));
                s[2*nt+1] = __fadd_rn(__fmul_rn(c[mt][nt][2*i+1], scale), __fmul_rn(m.y, -1e9f));
                *(float2*)(outF + grow*SQ + col) = make_float2(s[2*nt], s[2*nt+1]);
            }
            float mx = s[0];
            #pragma unroll
            for (int j = 1; j < 8; j++) mx = fmaxf(mx, s[j]);
            mx = fmaxf(mx, __shfl_xor_sync(0xffffffffu, mx, 1));
            mx = fmaxf(mx, __shfl_xor_sync(0xffffffffu, mx, 2));
            float es = 0.f;
            #pragma unroll
            for (int j = 0; j < 8; j++) es += __expf(s[j] - mx);
            es += __shfl_xor_sync(0xffffffffu, es, 1);
            es += __shfl_xor_sync(0xffffffffu, es, 2);
            if ((lane & 3) == 0) {
                smax[wn*128 + rowLocal] = mx;
                ssum[wn*128 + rowLocal] = es;
            }
        }
    __syncthreads();
    if (tid < 128) {
        float m = smax[tid];
        #pragma unroll
        for (int w = 1; w < 4; w++) m = fmaxf(m, smax[w*128 + tid]);
        float l = 0.f;
        #pragma unroll
        for (int w = 0; w < 4; w++)
            l += ssum[w*128 + tid] * __expf(smax[w*128 + tid] - m);
        const long long grow = (long long)blockIdx.z * SQ + bm + tid;
        g_s.tmax[grow*16 + blockIdx.x] = m;
        g_s.tsum[grow*16 + blockIdx.x] = l;
    }
}

// ============================================================================
// PV kernel: h = p @ v  (A = split normalized p, B = split v^T), fp32 out
// ============================================================================
__global__ __launch_bounds__(256, 2)
void pv_gemm(float* __restrict__ outF)
{
    extern __shared__ char smem[];
    const uint32_t sbu = smem_u32(smem);
    const int tid = threadIdx.x, lane = tid & 31, wid = tid >> 5;
    const int wm = wid >> 2, wn = wid & 3;
    const int bm = blockIdx.y << 7, bn = blockIdx.x << 7;

    float c[4][4][4];
    #pragma unroll
    for (int i = 0; i < 4; i++)
        #pragma unroll
        for (int j = 0; j < 4; j++)
            { c[i][j][0]=0.f; c[i][j][1]=0.f; c[i][j][2]=0.f; c[i][j][3]=0.f; }

    gemm_mainloop(sbu, tid, lane, wm, wn,
                  g_s.phi, g_s.plo, g_s.vthi, g_s.vtlo,
                  ((long long)blockIdx.z * SQ + bm) * SQ,
                  (long long)bn * MR + (long long)blockIdx.z * SQ,
                  SQ, MR, SQ >> 5, c);

    const int qrow = lane >> 2, qcol = (lane & 3) * 2;
    #pragma unroll
    for (int mt = 0; mt < 4; mt++)
        #pragma unroll
        for (int i = 0; i < 2; i++) {
            const long long grow = (long long)blockIdx.z * SQ + bm + wm*64 + mt*16 + qrow + i*8;
            #pragma unroll
            for (int nt = 0; nt < 4; nt++) {
                const int col = bn + wn*32 + nt*8 + qcol;
                *(float2*)(outF + grow*DQ + col) =
                    make_float2(c[mt][nt][2*i], c[mt][nt][2*i+1]);
            }
        }
}

// ============================================================================
// Elementwise input split: X fp32 -> (hi, lo) bf16, same layout
// ============================================================================
__global__ __launch_bounds__(256)
void x_split(const float* __restrict__ X, __nv_bfloat16* __restrict__ H,
             __nv_bfloat16* __restrict__ L)
{
    const size_t i = ((size_t)blockIdx.x * 256 + threadIdx.x) * 4;
    float4 v = *(const float4*)(X + i);
    uint32_t h0, l0, h1, l1;
    split2(v.x, v.y, h0, l0);
    split2(v.z, v.w, h1, l1);
    *(uint2*)(H + i) = make_uint2(h0, h1);
    *(uint2*)(L + i) = make_uint2(l0, l1);
}

// ============================================================================
// Weight transpose + split: Wt[d][f] = split(W[f][d])
// ============================================================================
__global__ __launch_bounds__(256)
void wt_split(const float* __restrict__ W, __nv_bfloat16* __restrict__ Th,
              __nv_bfloat16* __restrict__ Tl)
{
    const int e = blockIdx.x * 256 + threadIdx.x;
    const int f = e >> 9, dd = e & 511;
    float v = W[f * DQ + dd];
    __nv_bfloat16 h = __float2bfloat16(v);
    Th[dd * DQ + f] = h;
    Tl[dd * DQ + f] = __float2bfloat16(v - __bfloat162float(h));
}

// ============================================================================
// Softmax normalize + split: p = exp(s-m)/l (fp32 out) and (hi, lo) bf16
// ============================================================================
__global__ __launch_bounds__(256)
void softmax_norm_kernel(float* __restrict__ p)
{
    const int g = blockIdx.x;
    __shared__ float sh[2];
    if (threadIdx.x == 0) {
        float m = __int_as_float(0xff800000);
        #pragma unroll
        for (int t = 0; t < 16; t++) m = fmaxf(m, g_s.tmax[g * 16 + t]);
        float l = 0.f;
        #pragma unroll
        for (int t = 0; t < 16; t++)
            l += g_s.tsum[g * 16 + t] * __expf(g_s.tmax[g * 16 + t] - m);
        sh[0] = m;
        sh[1] = 1.f / l;
    }
    __syncthreads();
    const float m = sh[0], inv = sh[1];
    float* row = p + (size_t)g * SQ;
    __nv_bfloat16* ph = g_s.phi + (size_t)g * SQ;
    __nv_bfloat16* pl = g_s.plo + (size_t)g * SQ;
    #pragma unroll
    for (int it = 0; it < 2; it++) {
        const int i = (threadIdx.x << 2) + (it << 10);
        float4 v = *(float4*)&row[i];
        v.x = __expf(v.x - m) * inv;
        v.y = __expf(v.y - m) * inv;
        v.z = __expf(v.z - m) * inv;
        v.w = __expf(v.w - m) * inv;
        *(float4*)&row[i] = v;
        uint32_t h0, l0, h1, l1;
        split2(v.x, v.y, h0, l0);
        split2(v.z, v.w, h1, l1);
        *(uint2*)(ph + i) = make_uint2(h0, h1);
        *(uint2*)(pl + i) = make_uint2(l0, l1);
    }
}

// ============================================================================
// Host launcher (graph-capturable: kernel launches only)
// ============================================================================
extern "C" void kernel_launch(void* const* d_in, const int* in_sizes, int n_in,
                              void* d_out, int out_size)
{
    const float* qx   = (const float*)d_in[0];
    const float* kx   = (const float*)d_in[1];
    const float* vx   = (const float*)d_in[2];
    const float* mask = (const float*)d_in[3];
    const float* Wq   = (const float*)d_in[4];
    const float* Wk   = (const float*)d_in[5];
    const float* Wv   = (const float*)d_in[6];

    float* h = (float*)d_out;                  // [8,2048,512]
    float* p = h + (size_t)MR * DQ;            // [8,2048,2048]

    void* sbase = nullptr;
    cudaGetSymbolAddress(&sbase, g_s);
    Scratch* S = (Scratch*)sbase;

    static bool attr_done = false;
    if (!attr_done) {
        cudaFuncSetAttribute(proj_gemm, cudaFuncAttributeMaxDynamicSharedMemorySize, SM_TOTAL);
        cudaFuncSetAttribute(qk_gemm,   cudaFuncAttributeMaxDynamicSharedMemorySize, SM_TOTAL);
        cudaFuncSetAttribute(pv_gemm,   cudaFuncAttributeMaxDynamicSharedMemorySize, SM_TOTAL);
        attr_done = true;
    }

    const int nsplit = (MR * DQ) / 1024;   // 8192 blocks, 4 elems/thread

    // 1) split inputs + transpose/split weights
    x_split<<<nsplit, 256>>>(qx, S->xhi[0], S->xlo[0]);
    x_split<<<nsplit, 256>>>(kx, S->xhi[1], S->xlo[1]);
    x_split<<<nsplit, 256>>>(vx, S->xhi[2], S->xlo[2]);
    wt_split<<<1024, 256>>>(Wq, S->wthi[0], S->wtlo[0]);
    wt_split<<<1024, 256>>>(Wk, S->wthi[1], S->wtlo[1]);
    wt_split<<<1024, 256>>>(Wv, S->wthi[2], S->wtlo[2]);

    // 2) fused projections (z: 0=q, 1=k, 2=v-transposed)
    proj_gemm<<<dim3(4, 128, 3), 256, SM_TOTAL>>>();

    // 3) QK^T + scale + mask -> raw logits in p + per-tile stats
    qk_gemm<<<dim3(16, 16, NB), 256, SM_TOTAL>>>(p, mask);

    // 4) normalize p in place + emit split bf16 p
    softmax_norm_kernel<<<dim3(MR), 256>>>(p);

    // 5) h = p @ v
    pv_gemm<<<dim3(4, 16, NB), 256, SM_TOTAL>>>(h);
}